// round 17
// baseline (speedup 1.0000x reference)
#include <cuda_runtime.h>
#include <math_constants.h>
#include <cstdint>

// ---------------- problem constants ----------------
#define BATCHSZ 4096
#define DIM     256
#define NROWS   8192
#define NCH     16              // 512-col chunks
#define NPAIR   16              // chunk pairs per item
// prescale = sqrt(2 * log2(e)): product of two prescaled values = sim * 2 * log2e
#define PRESCALE 1.6986436f
#define LN2F     0.69314718055994531f

// ---------------- device scratch (no allocs allowed) ----------------
__device__ uint32_t g_afrag[64 * 16384];        // [rt][t16][ks][lane][4reg] 4MB
__device__ uint32_t g_bfrag[64 * 8 * 2048];     // [tile128][kc][nt][ks][lane][2reg] 4MB
__device__ float g_pm[NCH][NROWS];
__device__ float g_ps[NCH][NROWS];
__device__ float g_rsum[64];
__device__ unsigned int g_rtcount[64];          // zero-init; reset by final CTA
__device__ unsigned int g_fincount;             // zero-init; reset by final CTA

// ---------------- main-kernel smem layout (u32 words) ----------------
#define A_U32    16384                  // A tile fragments (64KB)
#define B_OFF    16384                  // 4 chunk buffers (two 16KB halves)
#define B_BUF    2048
#define RED_OFF  (B_OFF + 4 * B_BUF)    // 24576: merge scratch / pos / loss
#define SMEM_U32 (RED_OFF + 1024)
#define SMEM_BYTES (SMEM_U32 * 4)       // 102400

// ---------------- helpers ----------------
static __device__ __forceinline__ uint32_t f2bf2(float lo, float hi) {
    uint32_t r;   // d = {hi, lo}
    asm("cvt.rn.bf16x2.f32 %0, %1, %2;" : "=r"(r) : "f"(hi), "f"(lo));
    return r;
}
static __device__ __forceinline__ float ex2f(float x) {
    float y;
    asm("ex2.approx.ftz.f32 %0, %1;" : "=f"(y) : "f"(x));
    return y;
}
static __device__ __forceinline__ uint32_t smem_u32(const void* p) {
    uint32_t a;
    asm("{ .reg .u64 t; cvta.to.shared.u64 t, %1; cvt.u32.u64 %0, t; }" : "=r"(a) : "l"(p));
    return a;
}
static __device__ __forceinline__ void mma_bf16(float c[4],
        uint32_t a0, uint32_t a1, uint32_t a2, uint32_t a3,
        uint32_t b0, uint32_t b1) {
    asm volatile(
        "mma.sync.aligned.m16n8k16.row.col.f32.bf16.bf16.f32 "
        "{%0,%1,%2,%3}, {%4,%5,%6,%7}, {%8,%9}, {%0,%1,%2,%3};"
        : "+f"(c[0]), "+f"(c[1]), "+f"(c[2]), "+f"(c[3])
        : "r"(a0), "r"(a1), "r"(a2), "r"(a3), "r"(b0), "r"(b1));
}
#define CP_ASYNC16(dst, src) \
    asm volatile("cp.async.cg.shared.global [%0], [%1], 16;" :: "r"(dst), "l"(src))
#define CP_COMMIT() asm volatile("cp.async.commit_group;" ::: "memory")
#define CP_WAIT(n)  asm volatile("cp.async.wait_group %0;" :: "n"(n) : "memory")

// ==========================================================================
// Pre-pass v2 (coalesced): block b owns h-rows [b*32, b*32+32). Loads them
// coalesced into smem (pre-scaled fp32), then emits BOTH fragment layouts
// with linear (fully coalesced) global stores; gathers hit smem, not DRAM.
// ==========================================================================
#define PR_LD 260   // smem row stride (floats): 256 + 4, rotates banks
__global__ __launch_bounds__(256) void prep_kernel(const float* __restrict__ hi,
                                                   const float* __restrict__ hj) {
    __shared__ float sm[32 * PR_LD];
    const int tid = threadIdx.x;
    const int b = blockIdx.x;                   // 0..255
    const float* src = (b < 128) ? hi + (size_t)b * 32 * DIM
                                 : hj + (size_t)(b - 128) * 32 * DIM;

    // coalesced load 32x256 f32, pre-scaled
#pragma unroll
    for (int i = 0; i < 8; i++) {
        const int f = i * 256 + tid;            // float4 slot 0..2047
        const int row = f >> 6, kq = (f & 63) << 2;
        float4 v = *(const float4*)(src + (size_t)row * DIM + kq);
        float* d = sm + row * PR_LD + kq;
        d[0] = v.x * PRESCALE; d[1] = v.y * PRESCALE;
        d[2] = v.z * PRESCALE; d[3] = v.w * PRESCALE;
    }
    __syncthreads();

    // afrag: rows b*32..+31 live in rt = b>>2, t16 = (b&3)*2 + {0,1}.
    // Linear u over the 4096 output u32 -> coalesced STG.
    {
        const uint32_t aibase = (uint32_t)((b >> 2) * 16384 + (b & 3) * 2 * 2048);
#pragma unroll
        for (int i = 0; i < 16; i++) {
            const int u = i * 256 + tid;        // 0..4095
            const int t16l = u >> 11;
            const int ks = (u >> 7) & 15, l = (u >> 2) & 31, reg = u & 3;
            const int g = l >> 2, tq = l & 3;
            const int rowl = t16l * 16 + g + (reg & 1) * 8;
            const int k = ks * 16 + tq * 2 + ((reg >> 1) << 3);
            const float* s = sm + rowl * PR_LD + k;
            g_afrag[aibase + u] = f2bf2(s[0], s[1]);
        }
    }

    // bfrag: cols b*32..+31 live in tile ct4 = b>>2, nt = (b&3)*4 + {0..3}.
    {
        const int ct4 = b >> 2, ntbase = (b & 3) * 4;
#pragma unroll
        for (int i = 0; i < 16; i++) {
            const int u = i * 256 + tid;        // 0..4095
            const int ntl = u >> 10;
            const int kc = (u >> 7) & 7, ks = (u >> 6) & 1;
            const int l = (u >> 1) & 31, reg = u & 1;
            const int coll = ntl * 8 + (l >> 2);
            const int k = kc * 32 + ks * 16 + (l & 3) * 2 + reg * 8;
            const uint32_t bi = (uint32_t)(ct4 * 16384 + kc * 2048
                                 + (ntbase + ntl) * 128 + ks * 64 + l * 2 + reg);
            const float* s = sm + coll * PR_LD + k;
            g_bfrag[bi] = f2bf2(s[0], s[1]);
        }
    }
}

// ==========================================================================
// Fused bf16 mma.sync GEMM + online logsumexp (base-2) + fused tail.
// Item (CTA) = (row tile rt: 128 rows) x (512-col chunk ct); pair-granular
// cp.async pipeline (16 waits/syncs per item). Register-resident per-warp
// online LSE. Tail: 16th finisher per rt combines that tile's 16 chunk
// partials + computes pos; 64th rt-finisher emits the mean (all reductions
// fixed-order -> deterministic; counters self-reset for graph replay).
// ==========================================================================
__global__ __launch_bounds__(256, 2)
void ntxent_mma_kernel(const float* __restrict__ hi, const float* __restrict__ hj,
                       float* __restrict__ out) {
    extern __shared__ float smf[];
    uint32_t* smu = (uint32_t*)smf;
    const uint32_t sbase = smem_u32(smf);
    const int tid = threadIdx.x;
    const int w = tid >> 5, lane = tid & 31;
    const int g = lane >> 2, tq = lane & 3;
    const int wm = w >> 2, wn = w & 3;          // warp grid 2 x 4

    const int rt = blockIdx.x & 63;
    const int ct = blockIdx.x >> 6;             // 512-col chunk 0..15
    const int r0 = rt * 128;
    const int tdiag = (ct == (rt >> 2)) ? (rt & 3) : -1;

    const uint32_t* asrc = g_afrag + (size_t)rt * 16384;
    const uint32_t* bbase = g_bfrag + (size_t)ct * 65536;

    // -------- prologue: cp.async A tile (group), pair 0 (group) --------
#pragma unroll
    for (int i = 0; i < 16; i++) {
        const int ga = i * 256 + tid;
        CP_ASYNC16(sbase + ga * 16, asrc + ga * 4);
    }
    CP_COMMIT();
#pragma unroll
    for (int i = 0; i < 4; i++) {
        const int gi = i * 256 + tid;
        CP_ASYNC16(sbase + (B_OFF + gi * 4) * 4, bbase + gi * 4);
    }
    CP_COMMIT();

    float acc[4][4][4];
#pragma unroll
    for (int mf = 0; mf < 4; mf++)
#pragma unroll
        for (int nf = 0; nf < 4; nf++)
#pragma unroll
            for (int c = 0; c < 4; c++) acc[mf][nf][c] = 0.f;

    float rM[8], rS[8];
#pragma unroll
    for (int s = 0; s < 8; s++) { rM[s] = -CUDART_INF_F; rS[s] = 0.f; }

    for (int p = 0; p < NPAIR; p++) {
        CP_WAIT(0);                     // pair p resident
        __syncthreads();                // all warps done with the reused half

        if (p + 1 < NPAIR) {            // prefetch pair p+1 into other half
            const uint32_t boffu = (uint32_t)(B_OFF + (((p + 1) & 1) * 2) * B_BUF);
            const uint32_t* src = bbase + (size_t)(p + 1) * 4096;
#pragma unroll
            for (int i = 0; i < 4; i++) {
                const int gi = i * 256 + tid;
                CP_ASYNC16(sbase + (boffu + gi * 4) * 4, src + gi * 4);
            }
            CP_COMMIT();
        }

        // -------- MMA: 2 chunks x 2 k16-steps on pair p --------
        const uint32_t rdoff = (uint32_t)(B_OFF + ((p & 1) * 2) * B_BUF);
#pragma unroll
        for (int kc2 = 0; kc2 < 2; kc2++) {
            const int kc = (2 * p + kc2) & 7;
            const uint32_t* Bu = smu + rdoff + kc2 * B_BUF;
#pragma unroll
            for (int ksl = 0; ksl < 2; ksl++) {
                uint2 bfr[4];
#pragma unroll
                for (int nf = 0; nf < 4; nf++)
                    bfr[nf] = *(const uint2*)(Bu + ((wn * 4 + nf) * 2 + ksl) * 64
                                              + lane * 2);
#pragma unroll
                for (int mf = 0; mf < 4; mf++) {
                    const uint4 af = *(const uint4*)(smu
                        + ((wm * 4 + mf) * 16 + (kc * 2 + ksl)) * 128 + lane * 4);
#pragma unroll
                    for (int nf = 0; nf < 4; nf++)
                        mma_bf16(acc[mf][nf], af.x, af.y, af.z, af.w,
                                 bfr[nf].x, bfr[nf].y);
                }
            }
        }

        // -------- epilogue every 4 pairs (one 128-col tile done) --------
        if ((p & 3) == 3) {
            const int t = p >> 2;
            const bool hd = (t == tdiag);
            const int cloc = wn * 32 + tq * 2;
            const int rloc = wm * 64 + g;
#pragma unroll
            for (int mf = 0; mf < 4; mf++)
#pragma unroll
                for (int hh = 0; hh < 2; hh++) {
                    const int s = mf * 2 + hh;
                    float m = -CUDART_INF_F;
                    if (hd) {
                        const int gr = rloc + mf * 16 + hh * 8;
#pragma unroll
                        for (int nf = 0; nf < 4; nf++)
#pragma unroll
                            for (int c = 0; c < 2; c++) {
                                float v = acc[mf][nf][hh * 2 + c];
                                if (gr == cloc + nf * 8 + c) v = -CUDART_INF_F;
                                acc[mf][nf][hh * 2 + c] = v;
                                m = fmaxf(m, v);
                            }
                    } else {
#pragma unroll
                        for (int nf = 0; nf < 4; nf++)
#pragma unroll
                            for (int c = 0; c < 2; c++)
                                m = fmaxf(m, acc[mf][nf][hh * 2 + c]);
                    }
                    m = fmaxf(m, __shfl_xor_sync(0xffffffffu, m, 1));
                    m = fmaxf(m, __shfl_xor_sync(0xffffffffu, m, 2));
                    float sv = 0.f;
#pragma unroll
                    for (int nf = 0; nf < 4; nf++)
#pragma unroll
                        for (int c = 0; c < 2; c++)
                            sv += ex2f(acc[mf][nf][hh * 2 + c] - m);
                    sv += __shfl_xor_sync(0xffffffffu, sv, 1);
                    sv += __shfl_xor_sync(0xffffffffu, sv, 2);
                    const float nm = fmaxf(rM[s], m);
                    rS[s] = rS[s] * ex2f(rM[s] - nm) + sv * ex2f(m - nm);
                    rM[s] = nm;
#pragma unroll
                    for (int nf = 0; nf < 4; nf++)
#pragma unroll
                        for (int c = 0; c < 2; c++)
                            acc[mf][nf][hh * 2 + c] = 0.f;
                }
        }
    }

    // -------- cross-warp merge, publish this item's (m, s) partials --------
    {
        float* red = smf + RED_OFF;              // [wn][128 rows][m,s]
        if (tq == 0) {
#pragma unroll
            for (int s = 0; s < 8; s++) {
                const int row = wm * 64 + (s >> 1) * 16 + g + (s & 1) * 8;
                red[(wn * 128 + row) * 2 + 0] = rM[s];
                red[(wn * 128 + row) * 2 + 1] = rS[s];
            }
        }
        __syncthreads();
        if (tid < 128) {
            float M = red[tid * 2];
#pragma unroll
            for (int q = 1; q < 4; q++) M = fmaxf(M, red[(q * 128 + tid) * 2]);
            float S = 0.f;
#pragma unroll
            for (int q = 0; q < 4; q++)
                S += red[(q * 128 + tid) * 2 + 1] * ex2f(red[(q * 128 + tid) * 2] - M);
            g_pm[ct][r0 + tid] = M;
            g_ps[ct][r0 + tid] = S;
        }
    }

    // -------- fused tail: 16th chunk-finisher combines this row tile --------
    __shared__ bool s_last, s_final;
    __syncthreads();                             // g_pm/g_ps writes done block-wide
    if (tid == 0) {
        __threadfence();
        s_last = (atomicAdd(&g_rtcount[rt], 1u) == 15u);
    }
    __syncthreads();
    if (!s_last) return;
    __threadfence();                             // acquire all 16 items' partials

    float* spos = smf + RED_OFF;                 // 128 pos values (reuse, post-sync)
    float* sloss = smf + RED_OFF + 128;          // 128 row losses
    const int prbase = r0 & 4095;                // pair index base for these rows
    for (int i = 0; i < 16; i++) {               // 8 warps x 16 warp-dots
        const int pr = prbase + w * 16 + i;
        const float* pa = hi + (size_t)pr * DIM + lane * 8;
        const float* pb = hj + (size_t)pr * DIM + lane * 8;
        float4 x0 = *(const float4*)pa, x1 = *(const float4*)(pa + 4);
        float4 y0 = *(const float4*)pb, y1 = *(const float4*)(pb + 4);
        float d = x0.x * y0.x + x0.y * y0.y + x0.z * y0.z + x0.w * y0.w
                + x1.x * y1.x + x1.y * y1.y + x1.z * y1.z + x1.w * y1.w;
#pragma unroll
        for (int off = 16; off > 0; off >>= 1)
            d += __shfl_xor_sync(0xffffffffu, d, off);
        if (lane == 0) spos[w * 16 + i] = d;     // raw fp32 dot
    }
    __syncthreads();
    if (tid < 128) {
        const int r = r0 + tid;
        float M = g_pm[0][r];
#pragma unroll
        for (int c = 1; c < NCH; c++) M = fmaxf(M, g_pm[c][r]);
        float S = 0.f;
#pragma unroll
        for (int c = 0; c < NCH; c++) S += g_ps[c][r] * ex2f(g_pm[c][r] - M);
        sloss[tid] = LN2F * (M + __log2f(S)) - 2.0f * spos[tid];
    }
    __syncthreads();
    for (int stride = 64; stride > 0; stride >>= 1) {   // fixed-order tree
        if (tid < stride) sloss[tid] += sloss[tid + stride];
        __syncthreads();
    }
    if (tid == 0) {
        g_rsum[rt] = sloss[0];
        __threadfence();
        s_final = (atomicAdd(&g_fincount, 1u) == 63u);
    }
    __syncthreads();
    if (s_final) {
        if (tid == 0) {
            __threadfence();
            float s = 0.f;
#pragma unroll
            for (int r2 = 0; r2 < 64; r2++) s += g_rsum[r2];   // fixed order
            out[0] = s * (1.0f / NROWS);
            g_fincount = 0;                      // replay-safe resets
        }
        if (tid < 64) g_rtcount[tid] = 0;
    }
}

extern "C" void kernel_launch(void* const* d_in, const int* in_sizes, int n_in,
                              void* d_out, int out_size) {
    const float* hi = (const float*)d_in[0];
    const float* hj = (const float*)d_in[1];
    float* out = (float*)d_out;

    prep_kernel<<<256, 256>>>(hi, hj);
    cudaFuncSetAttribute(ntxent_mma_kernel,
                         cudaFuncAttributeMaxDynamicSharedMemorySize, SMEM_BYTES);
    ntxent_mma_kernel<<<64 * NCH, 256, SMEM_BYTES>>>(hi, hj, out);
}